// round 6
// baseline (speedup 1.0000x reference)
#include <cuda_runtime.h>
#include <cuda_fp16.h>
#include <cstdint>

// GCMCGraphConv fused kernel v6 (sm_100a)
//
//   pa = sigmoid(feat @ prob_w.T); rs = sigmoid(feat @ rsw.T)
//   rf = (feat @ review_w.T) * rs
//   out[d] += (weight[src]*pa + rf) * cj[src] * ci[d]
//
// v6 vs v5 (197us, L1 72.6%, issue 25.7%):
//  - edge meta (idx -> cj/ci gather, ~700cyc chain) issued at tile top but
//    CONSUMED after the GEMM: the gather latency hides under the mma work
//    instead of stalling the warp before it starts.
//  - A loads of a k-step batched ahead of all splits/mma (explicit MLP=4).
//  - otherwise identical to v5: reg budget 128, 2 blocks x 256 thr / SM.

#define OUT_DIM 64
#define THREADS 256
#define WARPS   8
#define TILE_E  256
#define NT      9

#define CBUF_FLOATS (32 * 64)
#define WBUF_FLOATS (CBUF_FLOATS + 32 * 4 + 32)
#define SMEM_FLOATS (WARPS * WBUF_FLOATS + NT * 4 * 32 * 4)
#define SMEM_BYTES  (SMEM_FLOATS * 4)

__device__ __forceinline__ void mma16816(float c[4],
    unsigned a0, unsigned a1, unsigned a2, unsigned a3,
    unsigned b0, unsigned b1)
{
    asm volatile(
      "mma.sync.aligned.m16n8k16.row.col.f32.f16.f16.f32 "
      "{%0,%1,%2,%3}, {%4,%5,%6,%7}, {%8,%9}, {%0,%1,%2,%3};\n"
      : "+f"(c[0]), "+f"(c[1]), "+f"(c[2]), "+f"(c[3])
      : "r"(a0), "r"(a1), "r"(a2), "r"(a3), "r"(b0), "r"(b1));
}

__device__ __forceinline__ void red_add_v4(float* p, float4 v) {
    asm volatile("red.global.add.v4.f32 [%0], {%1,%2,%3,%4};"
                 :: "l"(p), "f"(v.x), "f"(v.y), "f"(v.z), "f"(v.w) : "memory");
}

__device__ __forceinline__ unsigned packh2(float a, float b) {
    __half2 h = __floats2half2_rn(a, b);
    return *(unsigned*)&h;
}
__device__ __forceinline__ float2 h2f2(unsigned u) {
    __half2 h = *(__half2*)&u;
    return __half22float2(h);
}
__device__ __forceinline__ void split2(float a, float b, unsigned& hi, unsigned& lo) {
    hi = packh2(a, b);
    float2 f = h2f2(hi);
    lo = packh2(a - f.x, b - f.y);
}
__device__ __forceinline__ float sigmoidf_(float x) {
    return 1.f / (1.f + __expf(-x));
}

__global__ void __launch_bounds__(THREADS, 2)
gcmc_kernel(const float* __restrict__ weight,      // [N_SRC,64]
            const float* __restrict__ prob_w,      // [64]
            const float* __restrict__ rsw,         // [64]
            const float* __restrict__ review_w,    // [64,64]
            const float* __restrict__ feat,        // [E,64]
            const float* __restrict__ cj,          // [N_SRC]
            const float* __restrict__ ci,          // [N_DST]
            const int*   __restrict__ src_idx,     // [E]
            const int*   __restrict__ dst_idx,     // [E]
            float* __restrict__ out,               // [N_DST,64]
            int E, int n_tiles)
{
    extern __shared__ float smf[];

    const int tid  = threadIdx.x;
    const int lane = tid & 31;
    const int warp = tid >> 5;
    const int g    = lane >> 2;   // 0..7
    const int t    = lane & 3;    // 0..3

    float*  cbuf = smf + warp * WBUF_FLOATS;            // [32][64] rotated
    float4* rbuf = (float4*)(cbuf + CBUF_FLOATS);       // [32] {pa*cc, rs*cc, src, dst}
    float*  ccb  = cbuf + CBUF_FLOATS + 128;            // [32] cj*ci
    uint4 (*Btab)[4][32] = (uint4(*)[4][32])(smf + WARPS * WBUF_FLOATS);

    // ---- build B fragments once (fp16 hi/lo; slots k = 16ks+4t+{0..3}) ----
    for (int i = tid; i < NT * 4 * 32; i += THREADS) {
        int l  = i & 31;
        int ks = (i >> 5) & 3;
        int nt = i >> 7;
        int gg = l >> 2, tt = l & 3;
        int k0 = 16 * ks + 4 * tt;
        float w0 = 0.f, w1 = 0.f, w2 = 0.f, w3 = 0.f;
        if (nt < 8) {
            const float* W = review_w + (nt * 8 + gg) * OUT_DIM;
            w0 = W[k0]; w1 = W[k0 + 1]; w2 = W[k0 + 2]; w3 = W[k0 + 3];
        } else if (gg == 0) {   // gate col 64 = pa (prob_w)
            w0 = prob_w[k0]; w1 = prob_w[k0 + 1];
            w2 = prob_w[k0 + 2]; w3 = prob_w[k0 + 3];
        } else if (gg == 1) {   // gate col 65 = rs (review_score_w)
            w0 = rsw[k0]; w1 = rsw[k0 + 1];
            w2 = rsw[k0 + 2]; w3 = rsw[k0 + 3];
        }
        unsigned bh0, bl0, bh1, bl1;
        split2(w0, w1, bh0, bl0);
        split2(w2, w3, bh1, bl1);
        Btab[nt][ks][l] = make_uint4(bh0, bh1, bl0, bl1);
    }
    __syncthreads();

    const int rb = warp * 32;
    const int half = lane >> 4;      // epilogue: 0/1 -> which of 2 rows
    const int j    = lane & 15;      // epilogue: 16B chunk within row

    for (int tile = blockIdx.x; tile < n_tiles; tile += gridDim.x) {
        const int e0 = tile * TILE_E + rb;

        // ---- issue meta loads NOW, consume AFTER the GEMM ----
        int   m_s, m_d;
        float m_cj, m_ci;
        bool  m_v;
        {
            int e = e0 + lane;
            m_v = e < E;
            int ec = m_v ? e : E - 1;
            m_s = src_idx[ec];
            m_d = dst_idx[ec];
            m_cj = cj[m_s];
            m_ci = ci[m_d];
        }

        // ---- GEMM: [32 rows x 72 cols] straight from GMEM A ----
        float c[2][NT][4];
        #pragma unroll
        for (int mt = 0; mt < 2; mt++)
            #pragma unroll
            for (int nt = 0; nt < NT; nt++) {
                c[mt][nt][0] = 0.f; c[mt][nt][1] = 0.f;
                c[mt][nt][2] = 0.f; c[mt][nt][3] = 0.f;
            }

        const float* fA[2];
        const float* fB[2];
        #pragma unroll
        for (int mt = 0; mt < 2; mt++) {
            int ea = e0 + 16 * mt + g;
            int eb = ea + 8;
            fA[mt] = feat + (size_t)(ea < E ? ea : E - 1) * OUT_DIM;
            fB[mt] = feat + (size_t)(eb < E ? eb : E - 1) * OUT_DIM;
        }

        #pragma unroll
        for (int ks = 0; ks < 4; ks++) {
            const int ko = 16 * ks + 4 * t;
            // batch all 4 loads before any split/mma (explicit MLP)
            float4 v00 = *(const float4*)(fA[0] + ko);
            float4 v01 = *(const float4*)(fB[0] + ko);
            float4 v10 = *(const float4*)(fA[1] + ko);
            float4 v11 = *(const float4*)(fB[1] + ko);
            unsigned ah[2][4], al[2][4];
            split2(v00.x, v00.y, ah[0][0], al[0][0]);
            split2(v01.x, v01.y, ah[0][1], al[0][1]);
            split2(v00.z, v00.w, ah[0][2], al[0][2]);
            split2(v01.z, v01.w, ah[0][3], al[0][3]);
            split2(v10.x, v10.y, ah[1][0], al[1][0]);
            split2(v11.x, v11.y, ah[1][1], al[1][1]);
            split2(v10.z, v10.w, ah[1][2], al[1][2]);
            split2(v11.z, v11.w, ah[1][3], al[1][3]);
            #pragma unroll
            for (int nt = 0; nt < NT; nt++) {
                uint4 b = Btab[nt][ks][lane];
                #pragma unroll
                for (int mt = 0; mt < 2; mt++) {
                    mma16816(c[mt][nt], ah[mt][0], ah[mt][1], ah[mt][2], ah[mt][3], b.x, b.y);
                    mma16816(c[mt][nt], ah[mt][0], ah[mt][1], ah[mt][2], ah[mt][3], b.z, b.w);
                    mma16816(c[mt][nt], al[mt][0], al[mt][1], al[mt][2], al[mt][3], b.x, b.y);
                }
            }
        }

        // ---- commit meta (gathers have long since landed) ----
        {
            float cc = m_v ? m_cj * m_ci : 0.f;
            ccb[lane] = cc;
            ((float2*)&rbuf[lane])[1] =
                make_float2(__int_as_float(m_s), __int_as_float(m_d));
        }

        // ---- write c to warp-private smem (rotation ch2=(4nt+t+4(r&3))&31) ----
        #pragma unroll
        for (int mt = 0; mt < 2; mt++) {
            const int r0 = 16 * mt + g;
            const int rot = 4 * (r0 & 3);
            #pragma unroll
            for (int nt = 0; nt < 8; nt++) {
                const int ch2 = (4 * nt + t + rot) & 31;
                *(float2*)(cbuf + r0 * 64 + 2 * ch2) =
                    make_float2(c[mt][nt][0], c[mt][nt][1]);
                *(float2*)(cbuf + (r0 + 8) * 64 + 2 * ch2) =
                    make_float2(c[mt][nt][2], c[mt][nt][3]);
            }
        }
        __syncwarp();

        // gates: t==0 lanes hold cols 64(pa),65(rs); fold sigmoid * cjci
        if (t == 0) {
            #pragma unroll
            for (int mt = 0; mt < 2; mt++) {
                const int r0 = 16 * mt + g, r1 = r0 + 8;
                float cc0 = ccb[r0], cc1 = ccb[r1];
                ((float2*)&rbuf[r0])[0] = make_float2(
                    sigmoidf_(c[mt][8][0]) * cc0, sigmoidf_(c[mt][8][1]) * cc0);
                ((float2*)&rbuf[r1])[0] = make_float2(
                    sigmoidf_(c[mt][8][2]) * cc1, sigmoidf_(c[mt][8][3]) * cc1);
            }
        }
        __syncwarp();

        // ---- row-major epilogue: 2 edge rows per warp instruction ----
        #pragma unroll
        for (int i = 0; i < 16; i++) {
            const int r = 2 * i + half;
            float4 cv = *(const float4*)(cbuf + r * 64 + j * 4);
            const int cn2 = (2 * j - 4 * (r & 3)) & 31;   // even
            const int col = 2 * cn2;                       // 16B aligned
            float4 q = rbuf[r];                            // {paC, rsC, src, dst}
            int sx = __float_as_int(q.z);
            int dx = __float_as_int(q.w);
            float4 wv = *(const float4*)(weight + (size_t)sx * OUT_DIM + col);
            float4 o;
            o.x = fmaf(wv.x, q.x, cv.x * q.y);
            o.y = fmaf(wv.y, q.x, cv.y * q.y);
            o.z = fmaf(wv.z, q.x, cv.z * q.y);
            o.w = fmaf(wv.w, q.x, cv.w * q.y);
            red_add_v4(out + (size_t)dx * OUT_DIM + col, o);
        }
        __syncwarp();   // buffers reused next tile (warp-private)
    }
}

extern "C" void kernel_launch(void* const* d_in, const int* in_sizes, int n_in,
                              void* d_out, int out_size) {
    const float* weight   = (const float*)d_in[0];
    const float* prob_w   = (const float*)d_in[1];
    const float* rsw      = (const float*)d_in[2];
    const float* review_w = (const float*)d_in[3];
    const float* feat     = (const float*)d_in[4];
    const float* cj       = (const float*)d_in[5];
    const float* ci       = (const float*)d_in[6];
    const int*   src_idx  = (const int*)d_in[7];
    const int*   dst_idx  = (const int*)d_in[8];
    float* out = (float*)d_out;

    const int E = in_sizes[4] / OUT_DIM;
    const int n_tiles = (E + TILE_E - 1) / TILE_E;

    cudaMemsetAsync(d_out, 0, (size_t)out_size * sizeof(float), 0);

    static int smem_set = 0;
    if (!smem_set) {
        cudaFuncSetAttribute(gcmc_kernel,
                             cudaFuncAttributeMaxDynamicSharedMemorySize,
                             SMEM_BYTES);
        smem_set = 1;
    }

    int grid = n_tiles < 296 ? n_tiles : 296;   // 2 persistent blocks / SM
    gcmc_kernel<<<grid, THREADS, SMEM_BYTES, 0>>>(
        weight, prob_w, rsw, review_w, feat, cj, ci, src_idx, dst_idx,
        out, E, n_tiles);
}

// round 7
// speedup vs baseline: 1.0084x; 1.0084x over previous
#include <cuda_runtime.h>
#include <cuda_fp16.h>
#include <cstdint>

// GCMCGraphConv fused kernel v7 (sm_100a)
//
//   pa = sigmoid(feat @ prob_w.T); rs = sigmoid(feat @ rsw.T)
//   rf = (feat @ review_w.T) * rs
//   out[d] += (weight[src]*pa + rf) * cj[src] * ci[d]
//
// v7 = v5 (197us, best) with the third mma pass dropped:
//   2-pass fp16: ah*bh + ah*bl = ah*(b exactly). Only error is A's fp16
//   rounding (2^-11 rel) -> expected global rel_err ~2e-4 (< 1e-3 gate).
//   mma count -33%, A split work -50%, ~8 fewer live regs.
// v6's meta-hoist reverted (measured -3%).

#define OUT_DIM 64
#define THREADS 256
#define WARPS   8
#define TILE_E  256
#define NT      9

#define CBUF_FLOATS (32 * 64)
#define WBUF_FLOATS (CBUF_FLOATS + 32 * 4 + 32)
#define SMEM_FLOATS (WARPS * WBUF_FLOATS + NT * 4 * 32 * 4)
#define SMEM_BYTES  (SMEM_FLOATS * 4)

__device__ __forceinline__ void mma16816(float c[4],
    unsigned a0, unsigned a1, unsigned a2, unsigned a3,
    unsigned b0, unsigned b1)
{
    asm volatile(
      "mma.sync.aligned.m16n8k16.row.col.f32.f16.f16.f32 "
      "{%0,%1,%2,%3}, {%4,%5,%6,%7}, {%8,%9}, {%0,%1,%2,%3};\n"
      : "+f"(c[0]), "+f"(c[1]), "+f"(c[2]), "+f"(c[3])
      : "r"(a0), "r"(a1), "r"(a2), "r"(a3), "r"(b0), "r"(b1));
}

__device__ __forceinline__ void red_add_v4(float* p, float4 v) {
    asm volatile("red.global.add.v4.f32 [%0], {%1,%2,%3,%4};"
                 :: "l"(p), "f"(v.x), "f"(v.y), "f"(v.z), "f"(v.w) : "memory");
}

__device__ __forceinline__ unsigned packh2(float a, float b) {
    __half2 h = __floats2half2_rn(a, b);
    return *(unsigned*)&h;
}
__device__ __forceinline__ float2 h2f2(unsigned u) {
    __half2 h = *(__half2*)&u;
    return __half22float2(h);
}
__device__ __forceinline__ void split2(float a, float b, unsigned& hi, unsigned& lo) {
    hi = packh2(a, b);
    float2 f = h2f2(hi);
    lo = packh2(a - f.x, b - f.y);
}
__device__ __forceinline__ float sigmoidf_(float x) {
    return 1.f / (1.f + __expf(-x));
}

__global__ void __launch_bounds__(THREADS, 2)
gcmc_kernel(const float* __restrict__ weight,      // [N_SRC,64]
            const float* __restrict__ prob_w,      // [64]
            const float* __restrict__ rsw,         // [64]
            const float* __restrict__ review_w,    // [64,64]
            const float* __restrict__ feat,        // [E,64]
            const float* __restrict__ cj,          // [N_SRC]
            const float* __restrict__ ci,          // [N_DST]
            const int*   __restrict__ src_idx,     // [E]
            const int*   __restrict__ dst_idx,     // [E]
            float* __restrict__ out,               // [N_DST,64]
            int E, int n_tiles)
{
    extern __shared__ float smf[];

    const int tid  = threadIdx.x;
    const int lane = tid & 31;
    const int warp = tid >> 5;
    const int g    = lane >> 2;   // 0..7
    const int t    = lane & 3;    // 0..3

    float*  cbuf = smf + warp * WBUF_FLOATS;            // [32][64] rotated
    float4* rbuf = (float4*)(cbuf + CBUF_FLOATS);       // [32] {pa*cc, rs*cc, src, dst}
    float*  ccb  = cbuf + CBUF_FLOATS + 128;            // [32] cj*ci
    uint4 (*Btab)[4][32] = (uint4(*)[4][32])(smf + WARPS * WBUF_FLOATS);

    // ---- build B fragments once (fp16 hi/lo; slots k = 16ks+4t+{0..3}) ----
    for (int i = tid; i < NT * 4 * 32; i += THREADS) {
        int l  = i & 31;
        int ks = (i >> 5) & 3;
        int nt = i >> 7;
        int gg = l >> 2, tt = l & 3;
        int k0 = 16 * ks + 4 * tt;
        float w0 = 0.f, w1 = 0.f, w2 = 0.f, w3 = 0.f;
        if (nt < 8) {
            const float* W = review_w + (nt * 8 + gg) * OUT_DIM;
            w0 = W[k0]; w1 = W[k0 + 1]; w2 = W[k0 + 2]; w3 = W[k0 + 3];
        } else if (gg == 0) {   // gate col 64 = pa (prob_w)
            w0 = prob_w[k0]; w1 = prob_w[k0 + 1];
            w2 = prob_w[k0 + 2]; w3 = prob_w[k0 + 3];
        } else if (gg == 1) {   // gate col 65 = rs (review_score_w)
            w0 = rsw[k0]; w1 = rsw[k0 + 1];
            w2 = rsw[k0 + 2]; w3 = rsw[k0 + 3];
        }
        unsigned bh0, bl0, bh1, bl1;
        split2(w0, w1, bh0, bl0);
        split2(w2, w3, bh1, bl1);
        Btab[nt][ks][l] = make_uint4(bh0, bh1, bl0, bl1);
    }
    __syncthreads();

    const int rb = warp * 32;
    const int half = lane >> 4;      // epilogue: 0/1 -> which of 2 rows
    const int j    = lane & 15;      // epilogue: 16B chunk within row

    for (int tile = blockIdx.x; tile < n_tiles; tile += gridDim.x) {
        const int e0 = tile * TILE_E + rb;

        // ---- meta: 1 edge per lane -> ccb, rbuf.zw (src,dst) ----
        {
            int e = e0 + lane;
            bool v = e < E;
            int ec = v ? e : E - 1;
            int s_ = src_idx[ec], d_ = dst_idx[ec];
            float cc = v ? cj[s_] * ci[d_] : 0.f;
            ccb[lane] = cc;
            ((float2*)&rbuf[lane])[1] =
                make_float2(__int_as_float(s_), __int_as_float(d_));
        }
        __syncwarp();

        // ---- GEMM: [32 rows x 72 cols] straight from GMEM A (2-pass) ----
        float c[2][NT][4];
        #pragma unroll
        for (int mt = 0; mt < 2; mt++)
            #pragma unroll
            for (int nt = 0; nt < NT; nt++) {
                c[mt][nt][0] = 0.f; c[mt][nt][1] = 0.f;
                c[mt][nt][2] = 0.f; c[mt][nt][3] = 0.f;
            }

        const float* fA[2];
        const float* fB[2];
        #pragma unroll
        for (int mt = 0; mt < 2; mt++) {
            int ea = e0 + 16 * mt + g;
            int eb = ea + 8;
            fA[mt] = feat + (size_t)(ea < E ? ea : E - 1) * OUT_DIM;
            fB[mt] = feat + (size_t)(eb < E ? eb : E - 1) * OUT_DIM;
        }

        #pragma unroll
        for (int ks = 0; ks < 4; ks++) {
            const int ko = 16 * ks + 4 * t;
            unsigned ah[2][4];
            #pragma unroll
            for (int mt = 0; mt < 2; mt++) {
                float4 v0 = *(const float4*)(fA[mt] + ko);   // row g
                float4 v1 = *(const float4*)(fB[mt] + ko);   // row g+8
                ah[mt][0] = packh2(v0.x, v0.y);
                ah[mt][1] = packh2(v1.x, v1.y);
                ah[mt][2] = packh2(v0.z, v0.w);
                ah[mt][3] = packh2(v1.z, v1.w);
            }
            #pragma unroll
            for (int nt = 0; nt < NT; nt++) {
                uint4 b = Btab[nt][ks][lane];
                #pragma unroll
                for (int mt = 0; mt < 2; mt++) {
                    mma16816(c[mt][nt], ah[mt][0], ah[mt][1], ah[mt][2], ah[mt][3], b.x, b.y);
                    mma16816(c[mt][nt], ah[mt][0], ah[mt][1], ah[mt][2], ah[mt][3], b.z, b.w);
                }
            }
        }

        // ---- write c to warp-private smem (rotation ch2=(4nt+t+4(r&3))&31) ----
        #pragma unroll
        for (int mt = 0; mt < 2; mt++) {
            const int r0 = 16 * mt + g;
            const int rot = 4 * (r0 & 3);
            #pragma unroll
            for (int nt = 0; nt < 8; nt++) {
                const int ch2 = (4 * nt + t + rot) & 31;
                *(float2*)(cbuf + r0 * 64 + 2 * ch2) =
                    make_float2(c[mt][nt][0], c[mt][nt][1]);
                *(float2*)(cbuf + (r0 + 8) * 64 + 2 * ch2) =
                    make_float2(c[mt][nt][2], c[mt][nt][3]);
            }
        }
        // gates: t==0 lanes hold cols 64(pa),65(rs); fold sigmoid * cjci
        if (t == 0) {
            #pragma unroll
            for (int mt = 0; mt < 2; mt++) {
                const int r0 = 16 * mt + g, r1 = r0 + 8;
                float cc0 = ccb[r0], cc1 = ccb[r1];
                ((float2*)&rbuf[r0])[0] = make_float2(
                    sigmoidf_(c[mt][8][0]) * cc0, sigmoidf_(c[mt][8][1]) * cc0);
                ((float2*)&rbuf[r1])[0] = make_float2(
                    sigmoidf_(c[mt][8][2]) * cc1, sigmoidf_(c[mt][8][3]) * cc1);
            }
        }
        __syncwarp();

        // ---- row-major epilogue: 2 edge rows per warp instruction ----
        #pragma unroll
        for (int i = 0; i < 16; i++) {
            const int r = 2 * i + half;
            float4 cv = *(const float4*)(cbuf + r * 64 + j * 4);
            const int cn2 = (2 * j - 4 * (r & 3)) & 31;   // even
            const int col = 2 * cn2;                       // 16B aligned
            float4 q = rbuf[r];                            // {paC, rsC, src, dst}
            int sx = __float_as_int(q.z);
            int dx = __float_as_int(q.w);
            float4 wv = *(const float4*)(weight + (size_t)sx * OUT_DIM + col);
            float4 o;
            o.x = fmaf(wv.x, q.x, cv.x * q.y);
            o.y = fmaf(wv.y, q.x, cv.y * q.y);
            o.z = fmaf(wv.z, q.x, cv.z * q.y);
            o.w = fmaf(wv.w, q.x, cv.w * q.y);
            red_add_v4(out + (size_t)dx * OUT_DIM + col, o);
        }
        __syncwarp();   // buffers reused next tile (warp-private)
    }
}

extern "C" void kernel_launch(void* const* d_in, const int* in_sizes, int n_in,
                              void* d_out, int out_size) {
    const float* weight   = (const float*)d_in[0];
    const float* prob_w   = (const float*)d_in[1];
    const float* rsw      = (const float*)d_in[2];
    const float* review_w = (const float*)d_in[3];
    const float* feat     = (const float*)d_in[4];
    const float* cj       = (const float*)d_in[5];
    const float* ci       = (const float*)d_in[6];
    const int*   src_idx  = (const int*)d_in[7];
    const int*   dst_idx  = (const int*)d_in[8];
    float* out = (float*)d_out;

    const int E = in_sizes[4] / OUT_DIM;
    const int n_tiles = (E + TILE_E - 1) / TILE_E;

    cudaMemsetAsync(d_out, 0, (size_t)out_size * sizeof(float), 0);

    static int smem_set = 0;
    if (!smem_set) {
        cudaFuncSetAttribute(gcmc_kernel,
                             cudaFuncAttributeMaxDynamicSharedMemorySize,
                             SMEM_BYTES);
        smem_set = 1;
    }

    int grid = n_tiles < 296 ? n_tiles : 296;   // 2 persistent blocks / SM
    gcmc_kernel<<<grid, THREADS, SMEM_BYTES, 0>>>(
        weight, prob_w, rsw, review_w, feat, cj, ci, src_idx, dst_idx,
        out, E, n_tiles);
}

// round 9
// speedup vs baseline: 1.2162x; 1.2060x over previous
#include <cuda_runtime.h>
#include <cuda_fp16.h>
#include <cstdint>

// GCMCGraphConv fused kernel v9 (sm_100a)
//
//   pa = sigmoid(feat @ prob_w.T); rs = sigmoid(feat @ rsw.T)
//   rf = (feat @ review_w.T) * rs
//   out[d] += (weight[src]*pa + rf) * cj[src] * ci[d]
//
// v9 = v8's occupancy plan made real: v8's smem (89KB/blk) silently capped
// occupancy at 2 blocks. Here the per-warp transpose buffer is half2
// (4KB/warp), total 56KB/blk -> 3 blocks x 8 warps = 24 warps/SM, and the
// transpose STS + epilogue LDS wavefronts halve. nt-outer GEMM keeps only
// 8 accumulator floats live (peak ~72 regs, fits the 84-reg/occ-3 budget).
// 2-pass fp16 mma kept (rel_err ~2.2e-4 measured); fp16 c-store adds
// ~2^-11 on the rf term only -> expected rel_err ~2.7e-4 (< 1e-3).

#define OUT_DIM 64
#define THREADS 256
#define WARPS   8
#define TILE_E  256
#define NT      9

// per-warp: cbuf 32 rows x 32 half2 (4096B) + rbuf 32xfloat4 (512B) + ccb (128B)
#define WBUF_BYTES  (4096 + 512 + 128)
#define BTAB_OFF    (WARPS * WBUF_BYTES)
#define SMEM_BYTES  (BTAB_OFF + NT * 4 * 32 * 16)

__device__ __forceinline__ void mma16816(float c[4],
    unsigned a0, unsigned a1, unsigned a2, unsigned a3,
    unsigned b0, unsigned b1)
{
    asm volatile(
      "mma.sync.aligned.m16n8k16.row.col.f32.f16.f16.f32 "
      "{%0,%1,%2,%3}, {%4,%5,%6,%7}, {%8,%9}, {%0,%1,%2,%3};\n"
      : "+f"(c[0]), "+f"(c[1]), "+f"(c[2]), "+f"(c[3])
      : "r"(a0), "r"(a1), "r"(a2), "r"(a3), "r"(b0), "r"(b1));
}

__device__ __forceinline__ void red_add_v4(float* p, float4 v) {
    asm volatile("red.global.add.v4.f32 [%0], {%1,%2,%3,%4};"
                 :: "l"(p), "f"(v.x), "f"(v.y), "f"(v.z), "f"(v.w) : "memory");
}

__device__ __forceinline__ unsigned packh2(float a, float b) {
    __half2 h = __floats2half2_rn(a, b);
    return *(unsigned*)&h;
}
__device__ __forceinline__ float2 h2f2(unsigned u) {
    __half2 h = *(__half2*)&u;
    return __half22float2(h);
}
__device__ __forceinline__ void split2(float a, float b, unsigned& hi, unsigned& lo) {
    hi = packh2(a, b);
    float2 f = h2f2(hi);
    lo = packh2(a - f.x, b - f.y);
}
__device__ __forceinline__ float sigmoidf_(float x) {
    return 1.f / (1.f + __expf(-x));
}

__global__ void __launch_bounds__(THREADS, 3)
gcmc_kernel(const float* __restrict__ weight,      // [N_SRC,64]
            const float* __restrict__ prob_w,      // [64]
            const float* __restrict__ rsw,         // [64]
            const float* __restrict__ review_w,    // [64,64]
            const float* __restrict__ feat,        // [E,64]
            const float* __restrict__ cj,          // [N_SRC]
            const float* __restrict__ ci,          // [N_DST]
            const int*   __restrict__ src_idx,     // [E]
            const int*   __restrict__ dst_idx,     // [E]
            float* __restrict__ out,               // [N_DST,64]
            int E, int n_tiles)
{
    extern __shared__ char smraw[];

    const int tid  = threadIdx.x;
    const int lane = tid & 31;
    const int warp = tid >> 5;
    const int g    = lane >> 2;   // 0..7
    const int t    = lane & 3;    // 0..3

    char*   wbase = smraw + warp * WBUF_BYTES;
    unsigned* cbuf = (unsigned*)wbase;                 // [32 rows][32 half2]
    float4* rbuf = (float4*)(wbase + 4096);            // [32] {pa*cc, rs*cc, src, dst}
    float*  ccb  = (float*)(wbase + 4096 + 512);       // [32] cj*ci
    uint4 (*Btab)[4][32] = (uint4(*)[4][32])(smraw + BTAB_OFF);

    // ---- build B fragments once (fp16 hi/lo; slots k = 16ks+4t+{0..3}) ----
    for (int i = tid; i < NT * 4 * 32; i += THREADS) {
        int l  = i & 31;
        int ks = (i >> 5) & 3;
        int nt = i >> 7;
        int gg = l >> 2, tt = l & 3;
        int k0 = 16 * ks + 4 * tt;
        float w0 = 0.f, w1 = 0.f, w2 = 0.f, w3 = 0.f;
        if (nt < 8) {
            const float* W = review_w + (nt * 8 + gg) * OUT_DIM;
            w0 = W[k0]; w1 = W[k0 + 1]; w2 = W[k0 + 2]; w3 = W[k0 + 3];
        } else if (gg == 0) {   // gate col 64 = pa (prob_w)
            w0 = prob_w[k0]; w1 = prob_w[k0 + 1];
            w2 = prob_w[k0 + 2]; w3 = prob_w[k0 + 3];
        } else if (gg == 1) {   // gate col 65 = rs (review_score_w)
            w0 = rsw[k0]; w1 = rsw[k0 + 1];
            w2 = rsw[k0 + 2]; w3 = rsw[k0 + 3];
        }
        unsigned bh0, bl0, bh1, bl1;
        split2(w0, w1, bh0, bl0);
        split2(w2, w3, bh1, bl1);
        Btab[nt][ks][l] = make_uint4(bh0, bh1, bl0, bl1);
    }
    __syncthreads();

    const int rb = warp * 32;
    const int half = lane >> 4;      // epilogue: 0/1 -> which of 2 rows
    const int j    = lane & 15;      // epilogue: 8B chunk (4 cols) within row

    for (int tile = blockIdx.x; tile < n_tiles; tile += gridDim.x) {
        const int e0 = tile * TILE_E + rb;

        // ---- meta: 1 edge per lane -> ccb, rbuf.zw (src,dst) ----
        {
            int e = e0 + lane;
            bool v = e < E;
            int ec = v ? e : E - 1;
            int s_ = src_idx[ec], d_ = dst_idx[ec];
            float cc = v ? cj[s_] * ci[d_] : 0.f;
            ccb[lane] = cc;
            ((float2*)&rbuf[lane])[1] =
                make_float2(__int_as_float(s_), __int_as_float(d_));
        }
        __syncwarp();

        // ---- load ALL A fragments for this tile (16-deep LDG burst) ----
        unsigned a[2][4][4];   // [mt][ks][slot], packed fp16x2
        {
            const float* fA[2];
            const float* fB[2];
            #pragma unroll
            for (int mt = 0; mt < 2; mt++) {
                int ea = e0 + 16 * mt + g;
                int eb = ea + 8;
                fA[mt] = feat + (size_t)(ea < E ? ea : E - 1) * OUT_DIM;
                fB[mt] = feat + (size_t)(eb < E ? eb : E - 1) * OUT_DIM;
            }
            #pragma unroll
            for (int ks = 0; ks < 4; ks++) {
                const int ko = 16 * ks + 4 * t;
                #pragma unroll
                for (int mt = 0; mt < 2; mt++) {
                    float4 v0 = *(const float4*)(fA[mt] + ko);   // row g
                    float4 v1 = *(const float4*)(fB[mt] + ko);   // row g+8
                    a[mt][ks][0] = packh2(v0.x, v0.y);
                    a[mt][ks][1] = packh2(v1.x, v1.y);
                    a[mt][ks][2] = packh2(v0.z, v0.w);
                    a[mt][ks][3] = packh2(v1.z, v1.w);
                }
            }
        }

        // ---- GEMM nt-outer: 8 accum floats live; c -> half2 smem per nt ----
        #pragma unroll
        for (int nt = 0; nt < NT; nt++) {
            float c0[4] = {0.f, 0.f, 0.f, 0.f};
            float c1[4] = {0.f, 0.f, 0.f, 0.f};
            #pragma unroll
            for (int ks = 0; ks < 4; ks++) {
                uint4 b = Btab[nt][ks][lane];
                mma16816(c0, a[0][ks][0], a[0][ks][1], a[0][ks][2], a[0][ks][3], b.x, b.y);
                mma16816(c1, a[1][ks][0], a[1][ks][1], a[1][ks][2], a[1][ks][3], b.x, b.y);
                mma16816(c0, a[0][ks][0], a[0][ks][1], a[0][ks][2], a[0][ks][3], b.z, b.w);
                mma16816(c1, a[1][ks][0], a[1][ks][1], a[1][ks][2], a[1][ks][3], b.z, b.w);
            }
            if (nt < 8) {
                // slot ch2 = (4nt + t + 4*(r&3)) & 31; one half2 (2 cols) per slot
                {
                    const int r0 = g;
                    const int ch2 = (4 * nt + t + 4 * (r0 & 3)) & 31;
                    cbuf[r0 * 32 + ch2]       = packh2(c0[0], c0[1]);
                    cbuf[(r0 + 8) * 32 + ch2] = packh2(c0[2], c0[3]);
                }
                {
                    const int r0 = 16 + g;
                    const int ch2 = (4 * nt + t + 4 * (r0 & 3)) & 31;
                    cbuf[r0 * 32 + ch2]       = packh2(c1[0], c1[1]);
                    cbuf[(r0 + 8) * 32 + ch2] = packh2(c1[2], c1[3]);
                }
            } else if (t == 0) {
                // gate tile: cols 64(pa), 65(rs); fold sigmoid * cjci
                {
                    const int r0 = g, r1 = g + 8;
                    float cc0 = ccb[r0], cc1 = ccb[r1];
                    ((float2*)&rbuf[r0])[0] = make_float2(
                        sigmoidf_(c0[0]) * cc0, sigmoidf_(c0[1]) * cc0);
                    ((float2*)&rbuf[r1])[0] = make_float2(
                        sigmoidf_(c0[2]) * cc1, sigmoidf_(c0[3]) * cc1);
                }
                {
                    const int r0 = 16 + g, r1 = 24 + g;
                    float cc0 = ccb[r0], cc1 = ccb[r1];
                    ((float2*)&rbuf[r0])[0] = make_float2(
                        sigmoidf_(c1[0]) * cc0, sigmoidf_(c1[1]) * cc0);
                    ((float2*)&rbuf[r1])[0] = make_float2(
                        sigmoidf_(c1[2]) * cc1, sigmoidf_(c1[3]) * cc1);
                }
            }
        }
        __syncwarp();

        // ---- row-major epilogue: 2 edge rows per warp instruction ----
        #pragma unroll
        for (int i = 0; i < 16; i++) {
            const int r = 2 * i + half;
            // slots {2j, 2j+1} = 2 half2 = 4 columns
            uint2 cp = *(const uint2*)(cbuf + r * 32 + 2 * j);
            float2 lo = h2f2(cp.x), hi = h2f2(cp.y);
            const int cn2 = (2 * j - 4 * (r & 3)) & 31;   // even, no pair wrap
            const int col = 2 * cn2;                       // 16B aligned
            float4 q = rbuf[r];                            // {paC, rsC, src, dst}
            int sx = __float_as_int(q.z);
            int dx = __float_as_int(q.w);
            float4 wv = *(const float4*)(weight + (size_t)sx * OUT_DIM + col);
            float4 o;
            o.x = fmaf(wv.x, q.x, lo.x * q.y);
            o.y = fmaf(wv.y, q.x, lo.y * q.y);
            o.z = fmaf(wv.z, q.x, hi.x * q.y);
            o.w = fmaf(wv.w, q.x, hi.y * q.y);
            red_add_v4(out + (size_t)dx * OUT_DIM + col, o);
        }
        __syncwarp();   // buffers reused next tile (warp-private)
    }
}

extern "C" void kernel_launch(void* const* d_in, const int* in_sizes, int n_in,
                              void* d_out, int out_size) {
    const float* weight   = (const float*)d_in[0];
    const float* prob_w   = (const float*)d_in[1];
    const float* rsw      = (const float*)d_in[2];
    const float* review_w = (const float*)d_in[3];
    const float* feat     = (const float*)d_in[4];
    const float* cj       = (const float*)d_in[5];
    const float* ci       = (const float*)d_in[6];
    const int*   src_idx  = (const int*)d_in[7];
    const int*   dst_idx  = (const int*)d_in[8];
    float* out = (float*)d_out;

    const int E = in_sizes[4] / OUT_DIM;
    const int n_tiles = (E + TILE_E - 1) / TILE_E;

    cudaMemsetAsync(d_out, 0, (size_t)out_size * sizeof(float), 0);

    static int smem_set = 0;
    if (!smem_set) {
        cudaFuncSetAttribute(gcmc_kernel,
                             cudaFuncAttributeMaxDynamicSharedMemorySize,
                             SMEM_BYTES);
        smem_set = 1;
    }

    int grid = n_tiles < 444 ? n_tiles : 444;   // 3 persistent blocks / SM
    gcmc_kernel<<<grid, THREADS, SMEM_BYTES, 0>>>(
        weight, prob_w, rsw, review_w, feat, cj, ci, src_idx, dst_idx,
        out, E, n_tiles);
}

// round 10
// speedup vs baseline: 1.3408x; 1.1025x over previous
#include <cuda_runtime.h>
#include <cuda_fp16.h>
#include <cstdint>

// GCMCGraphConv fused kernel v10 (sm_100a)
//
//   pa = sigmoid(feat @ prob_w.T); rs = sigmoid(feat @ rsw.T)
//   rf = (feat @ review_w.T) * rs
//   out[d] += (weight[src]*pa + rf) * cj[src] * ci[d]
//
// v10 = v9 (167us, best; occ 36%, L1 80.8%) with the B lo-pass dropped:
//   single-pass fp16 mma. B-table LDS goes LDS.128 -> LDS.64 (144 -> 72 wf
//   per warp-tile, the largest L1 consumer), mma count halves, Btab smem
//   halves. Error: adds 2^-11 rounding on review_w -> expected rel_err
//   ~4.1e-4 (sqrt(2.97^2 + 2.8^2)), margin 2.4x under the 1e-3 gate.
// Everything else byte-identical to v9.

#define OUT_DIM 64
#define THREADS 256
#define WARPS   8
#define TILE_E  256
#define NT      9

// per-warp: cbuf 32 rows x 32 half2 (4096B) + rbuf 32xfloat4 (512B) + ccb (128B)
#define WBUF_BYTES  (4096 + 512 + 128)
#define BTAB_OFF    (WARPS * WBUF_BYTES)
#define SMEM_BYTES  (BTAB_OFF + NT * 4 * 32 * 8)

__device__ __forceinline__ void mma16816(float c[4],
    unsigned a0, unsigned a1, unsigned a2, unsigned a3,
    unsigned b0, unsigned b1)
{
    asm volatile(
      "mma.sync.aligned.m16n8k16.row.col.f32.f16.f16.f32 "
      "{%0,%1,%2,%3}, {%4,%5,%6,%7}, {%8,%9}, {%0,%1,%2,%3};\n"
      : "+f"(c[0]), "+f"(c[1]), "+f"(c[2]), "+f"(c[3])
      : "r"(a0), "r"(a1), "r"(a2), "r"(a3), "r"(b0), "r"(b1));
}

__device__ __forceinline__ void red_add_v4(float* p, float4 v) {
    asm volatile("red.global.add.v4.f32 [%0], {%1,%2,%3,%4};"
                 :: "l"(p), "f"(v.x), "f"(v.y), "f"(v.z), "f"(v.w) : "memory");
}

__device__ __forceinline__ unsigned packh2(float a, float b) {
    __half2 h = __floats2half2_rn(a, b);
    return *(unsigned*)&h;
}
__device__ __forceinline__ float2 h2f2(unsigned u) {
    __half2 h = *(__half2*)&u;
    return __half22float2(h);
}
__device__ __forceinline__ float sigmoidf_(float x) {
    return 1.f / (1.f + __expf(-x));
}

__global__ void __launch_bounds__(THREADS, 3)
gcmc_kernel(const float* __restrict__ weight,      // [N_SRC,64]
            const float* __restrict__ prob_w,      // [64]
            const float* __restrict__ rsw,         // [64]
            const float* __restrict__ review_w,    // [64,64]
            const float* __restrict__ feat,        // [E,64]
            const float* __restrict__ cj,          // [N_SRC]
            const float* __restrict__ ci,          // [N_DST]
            const int*   __restrict__ src_idx,     // [E]
            const int*   __restrict__ dst_idx,     // [E]
            float* __restrict__ out,               // [N_DST,64]
            int E, int n_tiles)
{
    extern __shared__ char smraw[];

    const int tid  = threadIdx.x;
    const int lane = tid & 31;
    const int warp = tid >> 5;
    const int g    = lane >> 2;   // 0..7
    const int t    = lane & 3;    // 0..3

    char*   wbase = smraw + warp * WBUF_BYTES;
    unsigned* cbuf = (unsigned*)wbase;                 // [32 rows][32 half2]
    float4* rbuf = (float4*)(wbase + 4096);            // [32] {pa*cc, rs*cc, src, dst}
    float*  ccb  = (float*)(wbase + 4096 + 512);       // [32] cj*ci
    uint2 (*Btab)[4][32] = (uint2(*)[4][32])(smraw + BTAB_OFF);

    // ---- build B fragments once (fp16, single-pass; k = 16ks+4t+{0..3}) ----
    for (int i = tid; i < NT * 4 * 32; i += THREADS) {
        int l  = i & 31;
        int ks = (i >> 5) & 3;
        int nt = i >> 7;
        int gg = l >> 2, tt = l & 3;
        int k0 = 16 * ks + 4 * tt;
        float w0 = 0.f, w1 = 0.f, w2 = 0.f, w3 = 0.f;
        if (nt < 8) {
            const float* W = review_w + (nt * 8 + gg) * OUT_DIM;
            w0 = W[k0]; w1 = W[k0 + 1]; w2 = W[k0 + 2]; w3 = W[k0 + 3];
        } else if (gg == 0) {   // gate col 64 = pa (prob_w)
            w0 = prob_w[k0]; w1 = prob_w[k0 + 1];
            w2 = prob_w[k0 + 2]; w3 = prob_w[k0 + 3];
        } else if (gg == 1) {   // gate col 65 = rs (review_score_w)
            w0 = rsw[k0]; w1 = rsw[k0 + 1];
            w2 = rsw[k0 + 2]; w3 = rsw[k0 + 3];
        }
        Btab[nt][ks][l] = make_uint2(packh2(w0, w1), packh2(w2, w3));
    }
    __syncthreads();

    const int rb = warp * 32;
    const int half = lane >> 4;      // epilogue: 0/1 -> which of 2 rows
    const int j    = lane & 15;      // epilogue: 8B chunk (4 cols) within row

    for (int tile = blockIdx.x; tile < n_tiles; tile += gridDim.x) {
        const int e0 = tile * TILE_E + rb;

        // ---- meta: 1 edge per lane -> ccb, rbuf.zw (src,dst) ----
        {
            int e = e0 + lane;
            bool v = e < E;
            int ec = v ? e : E - 1;
            int s_ = src_idx[ec], d_ = dst_idx[ec];
            float cc = v ? cj[s_] * ci[d_] : 0.f;
            ccb[lane] = cc;
            ((float2*)&rbuf[lane])[1] =
                make_float2(__int_as_float(s_), __int_as_float(d_));
        }
        __syncwarp();

        // ---- load ALL A fragments for this tile (16-deep LDG burst) ----
        unsigned a[2][4][4];   // [mt][ks][slot], packed fp16x2
        {
            const float* fA[2];
            const float* fB[2];
            #pragma unroll
            for (int mt = 0; mt < 2; mt++) {
                int ea = e0 + 16 * mt + g;
                int eb = ea + 8;
                fA[mt] = feat + (size_t)(ea < E ? ea : E - 1) * OUT_DIM;
                fB[mt] = feat + (size_t)(eb < E ? eb : E - 1) * OUT_DIM;
            }
            #pragma unroll
            for (int ks = 0; ks < 4; ks++) {
                const int ko = 16 * ks + 4 * t;
                #pragma unroll
                for (int mt = 0; mt < 2; mt++) {
                    float4 v0 = *(const float4*)(fA[mt] + ko);   // row g
                    float4 v1 = *(const float4*)(fB[mt] + ko);   // row g+8
                    a[mt][ks][0] = packh2(v0.x, v0.y);
                    a[mt][ks][1] = packh2(v1.x, v1.y);
                    a[mt][ks][2] = packh2(v0.z, v0.w);
                    a[mt][ks][3] = packh2(v1.z, v1.w);
                }
            }
        }

        // ---- GEMM nt-outer, single-pass: 8 accum floats live ----
        #pragma unroll
        for (int nt = 0; nt < NT; nt++) {
            float c0[4] = {0.f, 0.f, 0.f, 0.f};
            float c1[4] = {0.f, 0.f, 0.f, 0.f};
            #pragma unroll
            for (int ks = 0; ks < 4; ks++) {
                uint2 b = Btab[nt][ks][lane];
                mma16816(c0, a[0][ks][0], a[0][ks][1], a[0][ks][2], a[0][ks][3], b.x, b.y);
                mma16816(c1, a[1][ks][0], a[1][ks][1], a[1][ks][2], a[1][ks][3], b.x, b.y);
            }
            if (nt < 8) {
                // slot ch2 = (4nt + t + 4*(r&3)) & 31; one half2 (2 cols) per slot
                {
                    const int r0 = g;
                    const int ch2 = (4 * nt + t + 4 * (r0 & 3)) & 31;
                    cbuf[r0 * 32 + ch2]       = packh2(c0[0], c0[1]);
                    cbuf[(r0 + 8) * 32 + ch2] = packh2(c0[2], c0[3]);
                }
                {
                    const int r0 = 16 + g;
                    const int ch2 = (4 * nt + t + 4 * (r0 & 3)) & 31;
                    cbuf[r0 * 32 + ch2]       = packh2(c1[0], c1[1]);
                    cbuf[(r0 + 8) * 32 + ch2] = packh2(c1[2], c1[3]);
                }
            } else if (t == 0) {
                // gate tile: cols 64(pa), 65(rs); fold sigmoid * cjci
                {
                    const int r0 = g, r1 = g + 8;
                    float cc0 = ccb[r0], cc1 = ccb[r1];
                    ((float2*)&rbuf[r0])[0] = make_float2(
                        sigmoidf_(c0[0]) * cc0, sigmoidf_(c0[1]) * cc0);
                    ((float2*)&rbuf[r1])[0] = make_float2(
                        sigmoidf_(c0[2]) * cc1, sigmoidf_(c0[3]) * cc1);
                }
                {
                    const int r0 = 16 + g, r1 = 24 + g;
                    float cc0 = ccb[r0], cc1 = ccb[r1];
                    ((float2*)&rbuf[r0])[0] = make_float2(
                        sigmoidf_(c1[0]) * cc0, sigmoidf_(c1[1]) * cc0);
                    ((float2*)&rbuf[r1])[0] = make_float2(
                        sigmoidf_(c1[2]) * cc1, sigmoidf_(c1[3]) * cc1);
                }
            }
        }
        __syncwarp();

        // ---- row-major epilogue: 2 edge rows per warp instruction ----
        #pragma unroll
        for (int i = 0; i < 16; i++) {
            const int r = 2 * i + half;
            // slots {2j, 2j+1} = 2 half2 = 4 columns
            uint2 cp = *(const uint2*)(cbuf + r * 32 + 2 * j);
            float2 lo = h2f2(cp.x), hi = h2f2(cp.y);
            const int cn2 = (2 * j - 4 * (r & 3)) & 31;   // even, no pair wrap
            const int col = 2 * cn2;                       // 16B aligned
            float4 q = rbuf[r];                            // {paC, rsC, src, dst}
            int sx = __float_as_int(q.z);
            int dx = __float_as_int(q.w);
            float4 wv = *(const float4*)(weight + (size_t)sx * OUT_DIM + col);
            float4 o;
            o.x = fmaf(wv.x, q.x, lo.x * q.y);
            o.y = fmaf(wv.y, q.x, lo.y * q.y);
            o.z = fmaf(wv.z, q.x, hi.x * q.y);
            o.w = fmaf(wv.w, q.x, hi.y * q.y);
            red_add_v4(out + (size_t)dx * OUT_DIM + col, o);
        }
        __syncwarp();   // buffers reused next tile (warp-private)
    }
}

extern "C" void kernel_launch(void* const* d_in, const int* in_sizes, int n_in,
                              void* d_out, int out_size) {
    const float* weight   = (const float*)d_in[0];
    const float* prob_w   = (const float*)d_in[1];
    const float* rsw      = (const float*)d_in[2];
    const float* review_w = (const float*)d_in[3];
    const float* feat     = (const float*)d_in[4];
    const float* cj       = (const float*)d_in[5];
    const float* ci       = (const float*)d_in[6];
    const int*   src_idx  = (const int*)d_in[7];
    const int*   dst_idx  = (const int*)d_in[8];
    float* out = (float*)d_out;

    const int E = in_sizes[4] / OUT_DIM;
    const int n_tiles = (E + TILE_E - 1) / TILE_E;

    cudaMemsetAsync(d_out, 0, (size_t)out_size * sizeof(float), 0);

    static int smem_set = 0;
    if (!smem_set) {
        cudaFuncSetAttribute(gcmc_kernel,
                             cudaFuncAttributeMaxDynamicSharedMemorySize,
                             SMEM_BYTES);
        smem_set = 1;
    }

    int grid = n_tiles < 444 ? n_tiles : 444;   // 3 persistent blocks / SM
    gcmc_kernel<<<grid, THREADS, SMEM_BYTES, 0>>>(
        weight, prob_w, rsw, review_w, feat, cj, ci, src_idx, dst_idx,
        out, E, n_tiles);
}